// round 4
// baseline (speedup 1.0000x reference)
#include <cuda_runtime.h>

typedef unsigned long long u64;

// Problem constants
#define BB   8192
#define TT   80
#define HH   100
#define VV   100
#define G4   400
#define BCTA 56
#define ROWT 14      // ty groups (56/4) -- FAST index within warp
#define TXG  50      // tx groups (100/2 col-pairs)
#define NTHR 704     // 22 warps
#define NACT 700
#define NCTA 147

#define SMEM_L0 ((40000 + 5600) * 4 + 64 * 4)   // Whh0^T + h + tok
#define SMEM_GX ((40000 + 5600 + 400) * 4)      // Wih1^T + x + bias
#define SMEM_L1 ((40000 + 5600) * 4)            // Whh1^T + h

// ---------------- device scratch ----------------
__device__ float g_table0[VV * G4];                 // layer0 gate table (incl bias)
__device__ float g_Wt0 [HH * G4];                   // W_hh0^T [k][j]
__device__ float g_Wt1i[HH * G4];                   // W_ih1^T [k][j]
__device__ float g_Wt1h[HH * G4];                   // W_hh1^T [k][j]
__device__ float g_b1  [G4];
__device__ float g_h1[(size_t)TT * HH * BB + 64];   // layer0 out [t][k][b]
__device__ u64   g_gx[(size_t)TT * 200 * BB + 64];  // layer1 gate input, packed c-pairs [t][jp][b]
__device__ float g_h2[(size_t)HH * BB + 64];        // final h [k][b]

// ---------------- activations ----------------
__device__ __forceinline__ float sig_(float x) {
    return __fdividef(1.f, 1.f + __expf(-x));
}
__device__ __forceinline__ float tanh_(float x) {
    float e = __expf(2.f * x);
    return 1.f - __fdividef(2.f, e + 1.f);
}

// ---------------- packed f32x2 primitives ----------------
__device__ __forceinline__ void ffma2(u64& d, u64 a, u64 b) {
    asm("fma.rn.f32x2 %0, %1, %2, %0;" : "+l"(d) : "l"(a), "l"(b));
}
__device__ __forceinline__ u64 pack2(float lo, float hi) {
    u64 r; asm("mov.b64 %0, {%1, %2};" : "=l"(r) : "f"(lo), "f"(hi)); return r;
}
__device__ __forceinline__ float2 unpack2(u64 v) {
    float2 f; asm("mov.b64 {%0, %1}, %2;" : "=f"(f.x), "=f"(f.y) : "l"(v)); return f;
}

// ---------------- prep ----------------
__global__ void prep_kernel(const float* __restrict__ embed,
                            const float* __restrict__ Wih0,
                            const float* __restrict__ Whh0,
                            const float* __restrict__ bih0,
                            const float* __restrict__ bhh0,
                            const float* __restrict__ Wih1,
                            const float* __restrict__ Whh1,
                            const float* __restrict__ bih1,
                            const float* __restrict__ bhh1) {
    for (int idx = blockIdx.x * blockDim.x + threadIdx.x; idx < HH * G4;
         idx += gridDim.x * blockDim.x) {
        int k = idx / G4;
        int j = idx % G4;
        g_Wt0 [k * G4 + j] = Whh0[j * HH + k];
        g_Wt1i[k * G4 + j] = Wih1[j * HH + k];
        g_Wt1h[k * G4 + j] = Whh1[j * HH + k];
        float s = bih0[j] + bhh0[j];
        #pragma unroll
        for (int e = 0; e < 8; e++) s += Wih0[j * 8 + e] * embed[k * 8 + e];
        g_table0[k * G4 + j] = s;
        if (idx < G4) g_b1[idx] = bih1[idx] + bhh1[idx];
    }
}

// ---------------- packed register-blocked GEMM accumulate -------------------
// acc[g*4+r] (+)= W^T[k][g*100 + tx*2 .. +1] * in[k][b0 + ty*4 + r]
// 16 FFMA2 per k per thread; weights broadcast within warp (ty fast).
__device__ __forceinline__ void gemm_acc2(const float* __restrict__ ws,
                                          const float4* __restrict__ in4,
                                          int ty, int tx, u64 acc[16]) {
    const u64* wsu = (const u64*)ws;
    #pragma unroll 2
    for (int k = 0; k < HH; k++) {
        float4 h4 = in4[k * ROWT + ty];
        const u64* wr = wsu + k * 200 + tx;
        u64 wv0 = wr[0], wv1 = wr[50], wv2 = wr[100], wv3 = wr[150];
        u64 hp0 = pack2(h4.x, h4.x);
        u64 hp1 = pack2(h4.y, h4.y);
        u64 hp2 = pack2(h4.z, h4.z);
        u64 hp3 = pack2(h4.w, h4.w);
        ffma2(acc[0],  wv0, hp0); ffma2(acc[1],  wv0, hp1);
        ffma2(acc[2],  wv0, hp2); ffma2(acc[3],  wv0, hp3);
        ffma2(acc[4],  wv1, hp0); ffma2(acc[5],  wv1, hp1);
        ffma2(acc[6],  wv1, hp2); ffma2(acc[7],  wv1, hp3);
        ffma2(acc[8],  wv2, hp0); ffma2(acc[9],  wv2, hp1);
        ffma2(acc[10], wv2, hp2); ffma2(acc[11], wv2, hp3);
        ffma2(acc[12], wv3, hp0); ffma2(acc[13], wv3, hp1);
        ffma2(acc[14], wv3, hp2); ffma2(acc[15], wv3, hp3);
    }
}

// ---------------- LSTM cell elementwise + h store ---------------------------
__device__ __forceinline__ void cell_update2(u64 acc[16], float cst[4][2],
                                             float4* hs4, int ty, int tx) {
    float ho[4][2];
    #pragma unroll
    for (int r = 0; r < 4; r++) {
        float2 iv = unpack2(acc[0  + r]);
        float2 fv = unpack2(acc[4  + r]);
        float2 gv = unpack2(acc[8  + r]);
        float2 ov = unpack2(acc[12 + r]);
        {
            float i_ = sig_(iv.x), f_ = sig_(fv.x), g_ = tanh_(gv.x), o_ = sig_(ov.x);
            float cn = f_ * cst[r][0] + i_ * g_;
            cst[r][0] = cn;
            ho[r][0] = o_ * tanh_(cn);
        }
        {
            float i_ = sig_(iv.y), f_ = sig_(fv.y), g_ = tanh_(gv.y), o_ = sig_(ov.y);
            float cn = f_ * cst[r][1] + i_ * g_;
            cst[r][1] = cn;
            ho[r][1] = o_ * tanh_(cn);
        }
    }
    #pragma unroll
    for (int c = 0; c < 2; c++)
        hs4[(tx * 2 + c) * ROWT + ty] = make_float4(ho[0][c], ho[1][c], ho[2][c], ho[3][c]);
}

// ---------------- layer 0: sequential, table-driven input -------------------
__global__ void __launch_bounds__(NTHR, 1)
layer0_kernel(const int* __restrict__ x) {
    extern __shared__ float sm[];
    float* ws = sm;
    float* hs = sm + 40000;
    int*   tok = (int*)(sm + 45600);
    float4* hs4 = (float4*)hs;
    float4* gh14 = (float4*)g_h1;

    int tid = threadIdx.x, cta = blockIdx.x;
    int b0 = cta * BCTA;
    for (int i = tid; i < 10000; i += NTHR) ((float4*)ws)[i] = ((const float4*)g_Wt0)[i];
    for (int i = tid; i < 1400;  i += NTHR) hs4[i] = make_float4(0.f, 0.f, 0.f, 0.f);

    int ty = tid % ROWT, tx = tid / ROWT;   // ty FAST within warp (weight broadcast)
    bool act = tid < NACT;
    float cst[4][2] = {};
    u64 acc[16];

    for (int t = 0; t < TT; t++) {
        if (tid < BCTA) {
            int b = b0 + tid; if (b >= BB) b = BB - 1;
            tok[tid] = x[b * TT + t];
        }
        __syncthreads();
        if (act) {
            #pragma unroll
            for (int r = 0; r < 4; r++) {
                int tk = tok[ty * 4 + r];
                const u64* tp = (const u64*)g_table0 + tk * 200 + tx;
                acc[0  + r] = tp[0];
                acc[4  + r] = tp[50];
                acc[8  + r] = tp[100];
                acc[12 + r] = tp[150];
            }
            gemm_acc2(ws, hs4, ty, tx, acc);
        }
        __syncthreads();
        if (act) cell_update2(acc, cst, hs4, ty, tx);
        __syncthreads();
        int base = t * 204800 + cta * ROWT;
        for (int i = tid; i < 1400; i += NTHR) {
            int k = i / ROWT, bq = i % ROWT;
            if (b0 + bq * 4 + 3 < BB)
                gh14[base + k * 2048 + bq] = hs4[i];
        }
    }
}

// ---------------- gx: parallel W_ih1 GEMM over all t, weights resident ------
__global__ void __launch_bounds__(NTHR, 1)
gx_kernel() {
    extern __shared__ float sm[];
    float* ws = sm;
    float* xs = sm + 40000;
    float* b1s = sm + 45600;
    float4* xs4 = (float4*)xs;
    const float4* gh14 = (const float4*)g_h1;

    int tid = threadIdx.x, cta = blockIdx.x;
    int b0 = cta * BCTA;
    for (int i = tid; i < 10000; i += NTHR) ((float4*)ws)[i] = ((const float4*)g_Wt1i)[i];
    for (int i = tid; i < G4;    i += NTHR) b1s[i] = g_b1[i];

    int ty = tid % ROWT, tx = tid / ROWT;
    bool act = tid < NACT;
    bool strow = (b0 + ty * 4 + 3) < BB;
    u64 acc[16];

    for (int t = 0; t < TT; t++) {
        int base = t * 204800 + cta * ROWT;
        for (int i = tid; i < 1400; i += NTHR) {
            int k = i / ROWT, bq = i % ROWT;
            xs4[i] = gh14[base + k * 2048 + bq];
        }
        __syncthreads();
        if (act) {
            const u64* bp = (const u64*)b1s + tx;
            u64 bv0 = bp[0], bv1 = bp[50], bv2 = bp[100], bv3 = bp[150];
            #pragma unroll
            for (int r = 0; r < 4; r++) {
                acc[0 + r] = bv0; acc[4 + r] = bv1;
                acc[8 + r] = bv2; acc[12 + r] = bv3;
            }
            gemm_acc2(ws, xs4, ty, tx, acc);
            if (strow) {
                size_t tb = (size_t)t * 200 * BB;
                #pragma unroll
                for (int g = 0; g < 4; g++) {
                    int jp = g * 50 + tx;
                    u64* dst = g_gx + tb + (size_t)jp * BB + b0 + ty * 4;
                    ((ulonglong2*)dst)[0] = make_ulonglong2(acc[g * 4 + 0], acc[g * 4 + 1]);
                    ((ulonglong2*)dst)[1] = make_ulonglong2(acc[g * 4 + 2], acc[g * 4 + 3]);
                }
            }
        }
        __syncthreads();
    }
}

// ---------------- layer 1: sequential, W_hh1 resident ------------------------
__global__ void __launch_bounds__(NTHR, 1)
layer1_kernel() {
    extern __shared__ float sm[];
    float* ws = sm;
    float* hs = sm + 40000;
    float4* hs4 = (float4*)hs;

    int tid = threadIdx.x, cta = blockIdx.x;
    int b0 = cta * BCTA;
    for (int i = tid; i < 10000; i += NTHR) ((float4*)ws)[i] = ((const float4*)g_Wt1h)[i];
    for (int i = tid; i < 1400;  i += NTHR) hs4[i] = make_float4(0.f, 0.f, 0.f, 0.f);
    __syncthreads();

    int ty = tid % ROWT, tx = tid / ROWT;
    bool act = tid < NACT;
    float cst[4][2] = {};
    u64 acc[16];

    for (int t = 0; t < TT; t++) {
        if (act) {
            size_t tb = (size_t)t * 200 * BB;
            #pragma unroll
            for (int g = 0; g < 4; g++) {
                int jp = g * 50 + tx;
                const u64* src = g_gx + tb + (size_t)jp * BB + b0 + ty * 4;
                ulonglong2 q01 = ((const ulonglong2*)src)[0];
                ulonglong2 q23 = ((const ulonglong2*)src)[1];
                acc[g * 4 + 0] = q01.x; acc[g * 4 + 1] = q01.y;
                acc[g * 4 + 2] = q23.x; acc[g * 4 + 3] = q23.y;
            }
            gemm_acc2(ws, hs4, ty, tx, acc);
        }
        __syncthreads();
        if (act) cell_update2(acc, cst, hs4, ty, tx);
        __syncthreads();
    }
    for (int i = tid; i < 1400; i += NTHR) {
        int k = i / ROWT, bq = i % ROWT;
        if (b0 + bq * 4 + 3 < BB)
            ((float4*)g_h2)[k * 2048 + cta * ROWT + bq] = hs4[i];
    }
}

// ---------------- final FC ---------------------------------------------------
__global__ void __launch_bounds__(256, 1)
fc_kernel(const float* __restrict__ fcW, const float* __restrict__ fcb,
          float* __restrict__ out) {
    __shared__ float Ws[VV * HH];
    __shared__ float bs[VV];
    int tid = threadIdx.x;
    for (int i = tid; i < VV * HH; i += 256) Ws[i] = fcW[i];
    if (tid < VV) bs[tid] = fcb[tid];
    __syncthreads();

    int b = blockIdx.x * 256 + tid;
    float hr[HH];
    #pragma unroll
    for (int k = 0; k < HH; k++) hr[k] = g_h2[k * BB + b];

    const float4* Ws4 = (const float4*)Ws;
    float4* out4 = (float4*)out;
    #pragma unroll 1
    for (int v4 = 0; v4 < 25; v4++) {
        float a[4];
        #pragma unroll
        for (int q = 0; q < 4; q++) a[q] = bs[v4 * 4 + q];
        #pragma unroll
        for (int k4 = 0; k4 < 25; k4++) {
            #pragma unroll
            for (int q = 0; q < 4; q++) {
                float4 w = Ws4[(v4 * 4 + q) * 25 + k4];
                a[q] += hr[k4 * 4 + 0] * w.x + hr[k4 * 4 + 1] * w.y +
                        hr[k4 * 4 + 2] * w.z + hr[k4 * 4 + 3] * w.w;
            }
        }
        out4[b * 25 + v4] = make_float4(a[0], a[1], a[2], a[3]);
    }
}

// ---------------- launch ------------------------------------------------------
extern "C" void kernel_launch(void* const* d_in, const int* in_sizes, int n_in,
                              void* d_out, int out_size) {
    const int*   x     = (const int*)  d_in[0];
    const float* embed = (const float*)d_in[1];
    const float* Wih0  = (const float*)d_in[2];
    const float* Whh0  = (const float*)d_in[3];
    const float* bih0  = (const float*)d_in[4];
    const float* bhh0  = (const float*)d_in[5];
    const float* Wih1  = (const float*)d_in[6];
    const float* Whh1  = (const float*)d_in[7];
    const float* bih1  = (const float*)d_in[8];
    const float* bhh1  = (const float*)d_in[9];
    const float* fcW   = (const float*)d_in[10];
    const float* fcb   = (const float*)d_in[11];
    float* out = (float*)d_out;

    cudaFuncSetAttribute(layer0_kernel, cudaFuncAttributeMaxDynamicSharedMemorySize, SMEM_L0);
    cudaFuncSetAttribute(gx_kernel,     cudaFuncAttributeMaxDynamicSharedMemorySize, SMEM_GX);
    cudaFuncSetAttribute(layer1_kernel, cudaFuncAttributeMaxDynamicSharedMemorySize, SMEM_L1);

    prep_kernel<<<160, 256>>>(embed, Wih0, Whh0, bih0, bhh0, Wih1, Whh1, bih1, bhh1);
    layer0_kernel<<<NCTA, NTHR, SMEM_L0>>>(x);
    gx_kernel<<<NCTA, NTHR, SMEM_GX>>>();
    layer1_kernel<<<NCTA, NTHR, SMEM_L1>>>();
    fc_kernel<<<BB / 256, 256>>>(fcW, fcb, out);
}